// round 2
// baseline (speedup 1.0000x reference)
#include <cuda_runtime.h>

// Fused Swin window attention, fp32 baseline.
// One CTA per window (4096 CTAs, 256 threads, ~184KB smem).
// Pipeline per CTA: load x -> QKV gemm (smem-tiled) -> per-head scores(+bias+mask)
// -> softmax -> AV -> proj -> global write.

#define NT 256
#define XS 132   // row stride (floats) for 64x128 row-major buffers (pad for banks)
#define WS 68    // row stride for 128x64 c-major (transposed) buffers
#define SSPAD 68 // row stride for 64x64 score buffer

__global__ __launch_bounds__(NT, 1)
void winattn_kernel(const float* __restrict__ x,
                    const float* __restrict__ mask,
                    const float* __restrict__ qkv_w,
                    const float* __restrict__ qkv_b,
                    const float* __restrict__ proj_w,
                    const float* __restrict__ proj_b,
                    const float* __restrict__ bias_table,
                    float* __restrict__ out)
{
    extern __shared__ float sm[];
    float* sx  = sm;               // 64 x XS : x, later attention output O
    float* sq  = sx  + 64 * XS;    // 64 x XS : Q (scaled)
    float* sv  = sq  + 64 * XS;    // 64 x XS : V
    float* skT = sv  + 64 * XS;    // 128 x WS : K transposed [d][j]
    float* sw  = skT + 128 * WS;   // 128 x WS : weight tile, c-major [c][r]
    float* ss  = sw  + 128 * WS;   // 64 x SSPAD : per-head scores

    const int b   = blockIdx.x;
    const int tid = threadIdx.x;
    const int ty  = tid >> 4;   // 0..15 -> output row group (4 rows each)
    const int tx  = tid & 15;   // 0..15 -> output col group (4 cols each)
    const float SCALE = 0.17677669529663687f; // 32^-0.5

    // ---- load x window (64x128) ----
    {
        const float4* xg = (const float4*)(x + (size_t)b * 8192);
#pragma unroll
        for (int k = 0; k < 8; ++k) {
            int e = tid + k * NT;          // float4 index, 2048 total
            int r = e >> 5, c4 = e & 31;
            float4 v4 = xg[e];
            *(float4*)(sx + r * XS + c4 * 4) = v4;
        }
    }

    // ---- QKV gemm: qkv[i][r] = sum_c x[i][c]*W[r][c] + b[r] ----
    // 6 tiles of 64 W-rows. Tiles 0-1 -> Q, 2-3 -> K (transposed), 4-5 -> V.
    for (int wt = 0; wt < 6; ++wt) {
        const float4* wg = (const float4*)(qkv_w + wt * 8192);
#pragma unroll
        for (int k = 0; k < 8; ++k) {
            int e = tid + k * NT;
            int r = e >> 5, c4 = e & 31;   // local row r (0..63), col block
            float4 v4 = wg[e];
            sw[(c4 * 4 + 0) * WS + r] = v4.x;
            sw[(c4 * 4 + 1) * WS + r] = v4.y;
            sw[(c4 * 4 + 2) * WS + r] = v4.z;
            sw[(c4 * 4 + 3) * WS + r] = v4.w;
        }
        __syncthreads();

        float acc[4][4] = {};
#pragma unroll 4
        for (int c = 0; c < 128; ++c) {
            float4 wv = *(const float4*)(sw + c * WS + tx * 4);
#pragma unroll
            for (int ii = 0; ii < 4; ++ii) {
                float xv = sx[(ty * 4 + ii) * XS + c];
                acc[ii][0] = fmaf(xv, wv.x, acc[ii][0]);
                acc[ii][1] = fmaf(xv, wv.y, acc[ii][1]);
                acc[ii][2] = fmaf(xv, wv.z, acc[ii][2]);
                acc[ii][3] = fmaf(xv, wv.w, acc[ii][3]);
            }
        }
#pragma unroll
        for (int ii = 0; ii < 4; ++ii) {
            int i = ty * 4 + ii;
#pragma unroll
            for (int rr = 0; rr < 4; ++rr) {
                int rl = tx * 4 + rr;
                int r  = wt * 64 + rl;
                float v = acc[ii][rr] + qkv_b[r];
                if (wt < 2)       sq[i * XS + r] = v * SCALE;
                else if (wt < 4)  skT[(r - 128) * WS + i] = v;
                else              sv[i * XS + (r - 256)] = v;
            }
        }
        __syncthreads();
    }

    // ---- attention per head ----
    const float* mwin = mask + (size_t)(b & 63) * 4096; // window = b % nW
    for (int h = 0; h < 4; ++h) {
        const int dbase = h * 32;

        // scores s[i][j] = sum_d q[i][d]*k[j][d]   (q pre-scaled)
        float acc[4][4] = {};
#pragma unroll 4
        for (int d = 0; d < 32; ++d) {
            float4 kv = *(const float4*)(skT + (dbase + d) * WS + tx * 4);
#pragma unroll
            for (int ii = 0; ii < 4; ++ii) {
                float qv = sq[(ty * 4 + ii) * XS + dbase + d];
                acc[ii][0] = fmaf(qv, kv.x, acc[ii][0]);
                acc[ii][1] = fmaf(qv, kv.y, acc[ii][1]);
                acc[ii][2] = fmaf(qv, kv.z, acc[ii][2]);
                acc[ii][3] = fmaf(qv, kv.w, acc[ii][3]);
            }
        }
        // epilogue: + relative position bias + window mask
#pragma unroll
        for (int ii = 0; ii < 4; ++ii) {
            int i = ty * 4 + ii;
            int ih = i >> 3, iw = i & 7;
#pragma unroll
            for (int jj = 0; jj < 4; ++jj) {
                int j  = tx * 4 + jj;
                int jh = j >> 3, jw = j & 7;
                int idx = (ih - jh + 7) * 15 + (iw - jw + 7);
                ss[i * SSPAD + j] = acc[ii][jj]
                                  + bias_table[idx * 4 + h]
                                  + mwin[i * 64 + j];
            }
        }
        __syncthreads();

        // softmax: 4 threads per row (quad shuffles for reductions)
        {
            int row = tid >> 2, ql = tid & 3;
            float* srow = ss + row * SSPAD;
            float m = -1e30f;
#pragma unroll
            for (int j = 0; j < 16; ++j) m = fmaxf(m, srow[ql + j * 4]);
            m = fmaxf(m, __shfl_xor_sync(0xffffffffu, m, 1));
            m = fmaxf(m, __shfl_xor_sync(0xffffffffu, m, 2));
            float sum = 0.f;
#pragma unroll
            for (int j = 0; j < 16; ++j) {
                float e = __expf(srow[ql + j * 4] - m);
                srow[ql + j * 4] = e;
                sum += e;
            }
            sum += __shfl_xor_sync(0xffffffffu, sum, 1);
            sum += __shfl_xor_sync(0xffffffffu, sum, 2);
            float inv = 1.0f / sum;
#pragma unroll
            for (int j = 0; j < 16; ++j) srow[ql + j * 4] *= inv;
        }
        __syncthreads();

        // AV: o[i][d] = sum_j s[i][j]*v[j][d]; write into sx (x is dead)
        float oacc[4][2] = {};
#pragma unroll 4
        for (int j = 0; j < 64; ++j) {
            float2 vv = *(const float2*)(sv + j * XS + dbase + tx * 2);
#pragma unroll
            for (int ii = 0; ii < 4; ++ii) {
                float s = ss[(ty * 4 + ii) * SSPAD + j];
                oacc[ii][0] = fmaf(s, vv.x, oacc[ii][0]);
                oacc[ii][1] = fmaf(s, vv.y, oacc[ii][1]);
            }
        }
#pragma unroll
        for (int ii = 0; ii < 4; ++ii) {
            *(float2*)(sx + (ty * 4 + ii) * XS + dbase + tx * 2) =
                make_float2(oacc[ii][0], oacc[ii][1]);
        }
        __syncthreads();
    }

    // ---- proj: y[i][o] = sum_c O[i][c]*Wp[o][c] + pb[o] ----
    for (int pt = 0; pt < 2; ++pt) {
        const float4* wg = (const float4*)(proj_w + pt * 8192);
#pragma unroll
        for (int k = 0; k < 8; ++k) {
            int e = tid + k * NT;
            int r = e >> 5, c4 = e & 31;
            float4 v4 = wg[e];
            sw[(c4 * 4 + 0) * WS + r] = v4.x;
            sw[(c4 * 4 + 1) * WS + r] = v4.y;
            sw[(c4 * 4 + 2) * WS + r] = v4.z;
            sw[(c4 * 4 + 3) * WS + r] = v4.w;
        }
        __syncthreads();

        float acc[4][4] = {};
#pragma unroll 4
        for (int c = 0; c < 128; ++c) {
            float4 wv = *(const float4*)(sw + c * WS + tx * 4);
#pragma unroll
            for (int ii = 0; ii < 4; ++ii) {
                float ov = sx[(ty * 4 + ii) * XS + c];
                acc[ii][0] = fmaf(ov, wv.x, acc[ii][0]);
                acc[ii][1] = fmaf(ov, wv.y, acc[ii][1]);
                acc[ii][2] = fmaf(ov, wv.z, acc[ii][2]);
                acc[ii][3] = fmaf(ov, wv.w, acc[ii][3]);
            }
        }
        int o0 = pt * 64 + tx * 4;
        float4 pb = *(const float4*)(proj_b + o0);
#pragma unroll
        for (int ii = 0; ii < 4; ++ii) {
            int i = ty * 4 + ii;
            float4 r;
            r.x = acc[ii][0] + pb.x;
            r.y = acc[ii][1] + pb.y;
            r.z = acc[ii][2] + pb.z;
            r.w = acc[ii][3] + pb.w;
            *(float4*)(out + ((size_t)b * 64 + i) * 128 + o0) = r;
        }
        __syncthreads();
    }
}

extern "C" void kernel_launch(void* const* d_in, const int* in_sizes, int n_in,
                              void* d_out, int out_size)
{
    const float* x          = (const float*)d_in[0];
    const float* mask       = (const float*)d_in[1];
    const float* qkv_w      = (const float*)d_in[2];
    const float* qkv_b      = (const float*)d_in[3];
    const float* proj_w     = (const float*)d_in[4];
    const float* proj_b     = (const float*)d_in[5];
    const float* bias_table = (const float*)d_in[6];
    float* out = (float*)d_out;

    const int smem_bytes = (3 * 64 * XS + 2 * 128 * WS + 64 * SSPAD) * 4; // 188416
    cudaFuncSetAttribute(winattn_kernel,
                         cudaFuncAttributeMaxDynamicSharedMemorySize, smem_bytes);

    winattn_kernel<<<4096, NT, smem_bytes>>>(x, mask, qkv_w, qkv_b,
                                             proj_w, proj_b, bias_table, out);
}

// round 4
// speedup vs baseline: 3.0571x; 3.0571x over previous
#include <cuda_runtime.h>
#include <cstdint>

#define NT    256
#define SCALE 0.17677669529663687f
#define SA    132   // stride for sx/sq/sk/W tiles (4g+t bank perm -> conflict-free)
#define SP    65    // stride for P/score buffer (i+j bank perm -> conflict-free softmax)
#define SV    68    // stride for V^T
#define HP    (64*SP)  // per-head P block

__device__ __forceinline__ float tf32r(float x) {
    float r; asm("cvt.rna.tf32.f32 %0, %1;" : "=f"(r) : "f"(x)); return r;
}
__device__ __forceinline__ void mma8(float* c, uint32_t a0, uint32_t a1, uint32_t a2, uint32_t a3,
                                     uint32_t b0, uint32_t b1) {
    asm volatile(
        "mma.sync.aligned.m16n8k8.row.col.f32.tf32.tf32.f32 "
        "{%0,%1,%2,%3}, {%4,%5,%6,%7}, {%8,%9}, {%0,%1,%2,%3};\n"
        : "+f"(c[0]), "+f"(c[1]), "+f"(c[2]), "+f"(c[3])
        : "r"(a0), "r"(a1), "r"(a2), "r"(a3), "r"(b0), "r"(b1));
}

__global__ __launch_bounds__(NT, 1)
void winattn_mma(const float* __restrict__ x,
                 const float* __restrict__ mask,
                 const float* __restrict__ qkv_w,
                 const float* __restrict__ qkv_b,
                 const float* __restrict__ proj_w,
                 const float* __restrict__ proj_b,
                 const float* __restrict__ bias_table,
                 float* __restrict__ out)
{
    extern __shared__ float sm[];
    float* sx  = sm;            // 64 x SA : X, later O
    float* sq  = sm + 8448;     // 64 x SA : Q (scaled, tf32)
    float* sk  = sm + 16896;    // 64 x SA : K (tf32)
    float* svT = sm + 25344;    // 128 x SV : V^T (tf32)
    float* swp = sm + 34048;    // 16896 floats: W tiles (stride SA) / P 4x64xSP

    const int tid  = threadIdx.x;
    const int wid  = tid >> 5, lane = tid & 31;
    const int g    = lane >> 2, t = lane & 3;
    const int b    = blockIdx.x;
    const int r0   = (wid & 3) * 16;   // warp row base
    const int cwh  = wid >> 2;         // warp col half (0/1)

    // ---- load X (64x128), tf32 round ----
    {
        const float4* xg = (const float4*)(x + (size_t)b * 8192);
#pragma unroll
        for (int it = 0; it < 8; ++it) {
            int e = tid + it * NT;
            int row = e >> 5, c4 = (e & 31) * 4;
            float4 v = xg[e];
            float4 o; o.x = tf32r(v.x); o.y = tf32r(v.y); o.z = tf32r(v.z); o.w = tf32r(v.w);
            *(float4*)(sx + row * SA + c4) = o;
        }
    }

    // ---- QKV: 3 chunks of 128 W-rows ----
    for (int wt = 0; wt < 3; ++wt) {
        __syncthreads();
        {
            const float4* wg = (const float4*)(qkv_w + wt * 16384);
#pragma unroll
            for (int it = 0; it < 16; ++it) {
                int e = tid + it * NT;
                int row = e >> 5, c4 = (e & 31) * 4;
                float4 v = wg[e];
                float4 o; o.x = tf32r(v.x); o.y = tf32r(v.y); o.z = tf32r(v.z); o.w = tf32r(v.w);
                *(float4*)(swp + row * SA + c4) = o;
            }
        }
        __syncthreads();

        float c[8][4] = {};
        const float* A = sx + r0 * SA;
        const float* B = swp + (cwh * 64) * SA;
#pragma unroll
        for (int kk = 0; kk < 16; ++kk) {
            int k0 = kk * 8;
            const float* ap = A + g * SA + k0 + t;
            uint32_t a0 = __float_as_uint(ap[0]);
            uint32_t a1 = __float_as_uint(ap[8 * SA]);
            uint32_t a2 = __float_as_uint(ap[4]);
            uint32_t a3 = __float_as_uint(ap[8 * SA + 4]);
#pragma unroll
            for (int n = 0; n < 8; ++n) {
                const float* bp = B + (n * 8 + g) * SA + k0 + t;
                mma8(c[n], a0, a1, a2, a3, __float_as_uint(bp[0]), __float_as_uint(bp[4]));
            }
        }
        // epilogue: +bias, route to Q/K/V^T
#pragma unroll
        for (int n = 0; n < 8; ++n) {
            int col = cwh * 64 + n * 8 + 2 * t;     // local col in this 128-chunk
            int rg  = wt * 128 + col;
            float b0v = __ldg(qkv_b + rg), b1v = __ldg(qkv_b + rg + 1);
            int i = r0 + g;
            if (wt == 0) {
                sq[i * SA + col]           = tf32r((c[n][0] + b0v) * SCALE);
                sq[i * SA + col + 1]       = tf32r((c[n][1] + b1v) * SCALE);
                sq[(i + 8) * SA + col]     = tf32r((c[n][2] + b0v) * SCALE);
                sq[(i + 8) * SA + col + 1] = tf32r((c[n][3] + b1v) * SCALE);
            } else if (wt == 1) {
                sk[i * SA + col]           = tf32r(c[n][0] + b0v);
                sk[i * SA + col + 1]       = tf32r(c[n][1] + b1v);
                sk[(i + 8) * SA + col]     = tf32r(c[n][2] + b0v);
                sk[(i + 8) * SA + col + 1] = tf32r(c[n][3] + b1v);
            } else {
                svT[col * SV + i]           = tf32r(c[n][0] + b0v);
                svT[(col + 1) * SV + i]     = tf32r(c[n][1] + b1v);
                svT[col * SV + i + 8]       = tf32r(c[n][2] + b0v);
                svT[(col + 1) * SV + i + 8] = tf32r(c[n][3] + b1v);
            }
        }
    }
    __syncthreads();

    // ---- scores: 4 heads -> P buffer (swp, stride SP), raw fp32 + bias + mask ----
    const float* mwin = mask + (size_t)(b & 63) * 4096;
#pragma unroll
    for (int h = 0; h < 4; ++h) {
        float c[4][4] = {};
        const float* A = sq + r0 * SA + h * 32;
        const float* B = sk + (cwh * 32) * SA + h * 32;
#pragma unroll
        for (int kk = 0; kk < 4; ++kk) {
            int k0 = kk * 8;
            const float* ap = A + g * SA + k0 + t;
            uint32_t a0 = __float_as_uint(ap[0]);
            uint32_t a1 = __float_as_uint(ap[8 * SA]);
            uint32_t a2 = __float_as_uint(ap[4]);
            uint32_t a3 = __float_as_uint(ap[8 * SA + 4]);
#pragma unroll
            for (int n = 0; n < 4; ++n) {
                const float* bp = B + (n * 8 + g) * SA + k0 + t;
                mma8(c[n], a0, a1, a2, a3, __float_as_uint(bp[0]), __float_as_uint(bp[4]));
            }
        }
        float* sp = swp + h * HP;
#pragma unroll
        for (int n = 0; n < 4; ++n) {
            int j0 = cwh * 32 + n * 8 + 2 * t;
#pragma unroll
            for (int cc = 0; cc < 2; ++cc) {
                int j = j0 + cc, jh = j >> 3, jw = j & 7;
                int i = r0 + g;
                int idx = ((i >> 3) - jh + 7) * 15 + ((i & 7) - jw + 7);
                sp[i * SP + j] = c[n][cc] + __ldg(bias_table + idx * 4 + h) + __ldg(mwin + i * 64 + j);
                i += 8;
                idx = ((i >> 3) - jh + 7) * 15 + ((i & 7) - jw + 7);
                sp[i * SP + j] = c[n][cc + 2] + __ldg(bias_table + idx * 4 + h) + __ldg(mwin + i * 64 + j);
            }
        }
    }
    __syncthreads();

    // ---- softmax: one (head,row) per thread; SP=65 -> conflict-free ----
    {
        float* srow = swp + (tid >> 6) * HP + (tid & 63) * SP;
        float mx = -1e30f;
#pragma unroll
        for (int j = 0; j < 64; ++j) mx = fmaxf(mx, srow[j]);
        float sum = 0.f;
#pragma unroll
        for (int j = 0; j < 64; ++j) { float e = __expf(srow[j] - mx); srow[j] = e; sum += e; }
        float inv = 1.0f / sum;
#pragma unroll
        for (int j = 0; j < 64; ++j) srow[j] = tf32r(srow[j] * inv);
    }
    __syncthreads();

    // ---- AV: O[i][d] = P_h @ V_h, write into sx (X dead) ----
#pragma unroll
    for (int hh = 0; hh < 2; ++hh) {
        int h = cwh * 2 + hh;
        float c[4][4] = {};
        const float* A = swp + h * HP + r0 * SP;
        const float* B = svT + (h * 32) * SV;
#pragma unroll
        for (int kk = 0; kk < 8; ++kk) {
            int k0 = kk * 8;
            const float* ap = A + g * SP + k0 + t;
            uint32_t a0 = __float_as_uint(ap[0]);
            uint32_t a1 = __float_as_uint(ap[8 * SP]);
            uint32_t a2 = __float_as_uint(ap[4]);
            uint32_t a3 = __float_as_uint(ap[8 * SP + 4]);
#pragma unroll
            for (int n = 0; n < 4; ++n) {
                const float* bp = B + (n * 8 + g) * SV + k0 + t;
                mma8(c[n], a0, a1, a2, a3, __float_as_uint(bp[0]), __float_as_uint(bp[4]));
            }
        }
#pragma unroll
        for (int n = 0; n < 4; ++n) {
            int d = h * 32 + n * 8 + 2 * t;
            int i = r0 + g;
            sx[i * SA + d]           = tf32r(c[n][0]);
            sx[i * SA + d + 1]       = tf32r(c[n][1]);
            sx[(i + 8) * SA + d]     = tf32r(c[n][2]);
            sx[(i + 8) * SA + d + 1] = tf32r(c[n][3]);
        }
    }
    __syncthreads();

    // ---- load Wp into swp (P dead) ----
    {
        const float4* wg = (const float4*)proj_w;
#pragma unroll
        for (int it = 0; it < 16; ++it) {
            int e = tid + it * NT;
            int row = e >> 5, c4 = (e & 31) * 4;
            float4 v = wg[e];
            float4 o; o.x = tf32r(v.x); o.y = tf32r(v.y); o.z = tf32r(v.z); o.w = tf32r(v.w);
            *(float4*)(swp + row * SA + c4) = o;
        }
    }
    __syncthreads();

    // ---- proj: out = O @ Wp^T + pb ----
    {
        float c[8][4] = {};
        const float* A = sx + r0 * SA;
        const float* B = swp + (cwh * 64) * SA;
#pragma unroll
        for (int kk = 0; kk < 16; ++kk) {
            int k0 = kk * 8;
            const float* ap = A + g * SA + k0 + t;
            uint32_t a0 = __float_as_uint(ap[0]);
            uint32_t a1 = __float_as_uint(ap[8 * SA]);
            uint32_t a2 = __float_as_uint(ap[4]);
            uint32_t a3 = __float_as_uint(ap[8 * SA + 4]);
#pragma unroll
            for (int n = 0; n < 8; ++n) {
                const float* bp = B + (n * 8 + g) * SA + k0 + t;
                mma8(c[n], a0, a1, a2, a3, __float_as_uint(bp[0]), __float_as_uint(bp[4]));
            }
        }
#pragma unroll
        for (int n = 0; n < 8; ++n) {
            int col = cwh * 64 + n * 8 + 2 * t;
            float pb0 = __ldg(proj_b + col), pb1 = __ldg(proj_b + col + 1);
            int i = r0 + g;
            float2 v0 = make_float2(c[n][0] + pb0, c[n][1] + pb1);
            float2 v1 = make_float2(c[n][2] + pb0, c[n][3] + pb1);
            *(float2*)(out + ((size_t)b * 64 + i) * 128 + col)       = v0;
            *(float2*)(out + ((size_t)b * 64 + i + 8) * 128 + col)   = v1;
        }
    }
}

extern "C" void kernel_launch(void* const* d_in, const int* in_sizes, int n_in,
                              void* d_out, int out_size)
{
    const float* x          = (const float*)d_in[0];
    const float* mask       = (const float*)d_in[1];
    const float* qkv_w      = (const float*)d_in[2];
    const float* qkv_b      = (const float*)d_in[3];
    const float* proj_w     = (const float*)d_in[4];
    const float* proj_b     = (const float*)d_in[5];
    const float* bias_table = (const float*)d_in[6];
    float* out = (float*)d_out;

    const int smem_bytes = (34048 + 16896) * 4;   // 203776
    cudaFuncSetAttribute(winattn_mma,
                         cudaFuncAttributeMaxDynamicSharedMemorySize, smem_bytes);
    winattn_mma<<<4096, NT, smem_bytes>>>(x, mask, qkv_w, qkv_b,
                                          proj_w, proj_b, bias_table, out);
}